// round 1
// baseline (speedup 1.0000x reference)
#include <cuda_runtime.h>

// Problem constants
#define C_IN    256
#define S_SEQ   90
#define K_DIM   180          // E*S = 2*90
#define B_BATCH 4096
#define N_OUT   2086
#define NPAD    2176         // padded N for fcwT (mult of 128, float4-aligned rows)

// Scratch (static device globals; no allocation)
__device__ float g_flatT[K_DIM * B_BATCH];   // [k][b]  (activation, transposed)
__device__ float g_fcwT [K_DIM * NPAD];      // [k][n]  (fc weight, transposed, zero-padded)

// ---------------------------------------------------------------------------
// Kernel 0: transpose fc_w [2086,180] -> fcwT [180,2176] (zero pad)
// ---------------------------------------------------------------------------
__global__ void transpose_fcw_kernel(const float* __restrict__ fc_w) {
    int i = blockIdx.x * 256 + threadIdx.x;
    if (i < K_DIM * NPAD) {
        int k = i / NPAD;
        int n = i - k * NPAD;
        g_fcwT[i] = (n < N_OUT) ? fc_w[n * K_DIM + k] : 0.0f;
    }
}

// ---------------------------------------------------------------------------
// Kernel 1: conv1x1 + BN + 2-head (head_dim=1) attention + out_proj
// One block per batch element. Writes flatT[k][b].
// ---------------------------------------------------------------------------
__global__ __launch_bounds__(96) void head_kernel(
    const float* __restrict__ x,
    const float* __restrict__ conv_w,
    const float* __restrict__ bn_gamma, const float* __restrict__ bn_beta,
    const float* __restrict__ bn_mean,  const float* __restrict__ bn_var,
    const float* __restrict__ in_proj_w, const float* __restrict__ in_proj_b,
    const float* __restrict__ out_proj_w, const float* __restrict__ out_proj_b)
{
    __shared__ float sw0[C_IN], sw1[C_IN];
    __shared__ float sk0[S_SEQ], sk1[S_SEQ], sv0[S_SEQ], sv1[S_SEQ];
    __shared__ float sred[4];   // kmax0, kmin0, kmax1, kmin1

    const int b = blockIdx.x;
    const int t = threadIdx.x;

    for (int i = t; i < C_IN; i += 96) {
        sw0[i] = conv_w[i];
        sw1[i] = conv_w[C_IN + i];
    }
    __syncthreads();

    float q0 = 0.f, q1 = 0.f;
    if (t < S_SEQ) {
        const float* xb = x + (size_t)b * (C_IN * S_SEQ) + t;
        float a0 = 0.f, a1 = 0.f;
#pragma unroll 8
        for (int c = 0; c < C_IN; ++c) {
            float xv = __ldg(xb + c * S_SEQ);
            a0 = fmaf(sw0[c], xv, a0);
            a1 = fmaf(sw1[c], xv, a1);
        }
        // BatchNorm (inference)
        float s0 = bn_gamma[0] * rsqrtf(bn_var[0] + 1e-5f);
        float s1 = bn_gamma[1] * rsqrtf(bn_var[1] + 1e-5f);
        float y0 = fmaf(a0, s0, bn_beta[0] - bn_mean[0] * s0);
        float y1 = fmaf(a1, s1, bn_beta[1] - bn_mean[1] * s1);
        // packed QKV projection (in_proj_w is [6,2] row-major)
        q0     = fmaf(y0, in_proj_w[0],  fmaf(y1, in_proj_w[1],  in_proj_b[0]));
        q1     = fmaf(y0, in_proj_w[2],  fmaf(y1, in_proj_w[3],  in_proj_b[1]));
        sk0[t] = fmaf(y0, in_proj_w[4],  fmaf(y1, in_proj_w[5],  in_proj_b[2]));
        sk1[t] = fmaf(y0, in_proj_w[6],  fmaf(y1, in_proj_w[7],  in_proj_b[3]));
        sv0[t] = fmaf(y0, in_proj_w[8],  fmaf(y1, in_proj_w[9],  in_proj_b[4]));
        sv1[t] = fmaf(y0, in_proj_w[10], fmaf(y1, in_proj_w[11], in_proj_b[5]));
    }
    __syncthreads();

    // per-head k max/min (for exact, stable softmax: m_i = max(q_i*kmax, q_i*kmin))
    if (t < 64) {
        int h = t >> 5, lane = t & 31;
        const float* kk = h ? sk1 : sk0;
        float mx = -3.4e38f, mn = 3.4e38f;
        for (int j = lane; j < S_SEQ; j += 32) {
            float kv = kk[j];
            mx = fmaxf(mx, kv);
            mn = fminf(mn, kv);
        }
        for (int o = 16; o > 0; o >>= 1) {
            mx = fmaxf(mx, __shfl_xor_sync(0xffffffffu, mx, o));
            mn = fminf(mn, __shfl_xor_sync(0xffffffffu, mn, o));
        }
        if (lane == 0) { sred[h * 2] = mx; sred[h * 2 + 1] = mn; }
    }
    __syncthreads();

    if (t < S_SEQ) {
        float m0 = fmaxf(q0 * sred[0], q0 * sred[1]);
        float m1 = fmaxf(q1 * sred[2], q1 * sred[3]);
        float d0 = 0.f, n0 = 0.f, d1 = 0.f, n1 = 0.f;
#pragma unroll 5
        for (int j = 0; j < S_SEQ; ++j) {
            float e0 = __expf(fmaf(q0, sk0[j], -m0));
            float e1 = __expf(fmaf(q1, sk1[j], -m1));
            d0 += e0; n0 = fmaf(e0, sv0[j], n0);
            d1 += e1; n1 = fmaf(e1, sv1[j], n1);
        }
        float o0 = n0 / d0, o1 = n1 / d1;
        // out_proj [2,2] row-major
        float f0 = fmaf(o0, out_proj_w[0], fmaf(o1, out_proj_w[1], out_proj_b[0]));
        float f1 = fmaf(o0, out_proj_w[2], fmaf(o1, out_proj_w[3], out_proj_b[1]));
        g_flatT[t * B_BATCH + b]           = f0;   // k = 0*90 + s
        g_flatT[(S_SEQ + t) * B_BATCH + b] = f1;   // k = 1*90 + s
    }
}

// ---------------------------------------------------------------------------
// Kernel 2: logits = flat @ fc_w^T + fc_b   (M=4096, N=2086, K=180), fp32
// 128x128 block tile, 8x8 per-thread micro-tile, packed f32x2 FMA.
// ---------------------------------------------------------------------------
__device__ __forceinline__ unsigned long long splat2(float a) {
    unsigned long long r;
    asm("mov.b64 %0, {%1, %1};" : "=l"(r) : "f"(a));
    return r;
}
__device__ __forceinline__ void ffma2(unsigned long long& d,
                                      unsigned long long a,
                                      unsigned long long b) {
    asm("fma.rn.f32x2 %0, %1, %2, %0;" : "+l"(d) : "l"(a), "l"(b));
}

__global__ __launch_bounds__(256, 1) void fc_kernel(
    const float* __restrict__ fc_b, float* __restrict__ out)
{
    extern __shared__ float sm[];
    float* sA = sm;                 // [180][128]  (k-major activation tile)
    float* sB = sm + K_DIM * 128;   // [180][128]  (k-major weight tile)

    const int tid = threadIdx.x;
    const int m0 = blockIdx.y * 128;
    const int n0 = blockIdx.x * 128;

    // stage both tiles: fully coalesced float4, conflict-free STS (contiguous)
    for (int i = tid; i < K_DIM * 32; i += 256) {
        int k = i >> 5, g = i & 31;
        *(float4*)(sA + k * 128 + g * 4) =
            *(const float4*)(g_flatT + k * B_BATCH + m0 + g * 4);
        *(float4*)(sB + k * 128 + g * 4) =
            *(const float4*)(g_fcwT + k * NPAD + n0 + g * 4);
    }
    __syncthreads();

    const int tx = tid & 15, ty = tid >> 4;     // n-dir, m-dir
    unsigned long long acc[8][4];
#pragma unroll
    for (int i = 0; i < 8; ++i)
#pragma unroll
        for (int j = 0; j < 4; ++j) acc[i][j] = 0ull;

    const float* pa = sA + ty * 8;
    const unsigned long long* pb = (const unsigned long long*)(sB) + tx * 4;

#pragma unroll 4
    for (int k = 0; k < K_DIM; ++k) {
        unsigned long long b0 = pb[k * 64 + 0];
        unsigned long long b1 = pb[k * 64 + 1];
        unsigned long long b2 = pb[k * 64 + 2];
        unsigned long long b3 = pb[k * 64 + 3];
        float4 a0 = *(const float4*)(pa + k * 128);
        float4 a1 = *(const float4*)(pa + k * 128 + 4);
        float av[8] = {a0.x, a0.y, a0.z, a0.w, a1.x, a1.y, a1.z, a1.w};
#pragma unroll
        for (int mi = 0; mi < 8; ++mi) {
            unsigned long long ap = splat2(av[mi]);
            ffma2(acc[mi][0], ap, b0);
            ffma2(acc[mi][1], ap, b1);
            ffma2(acc[mi][2], ap, b2);
            ffma2(acc[mi][3], ap, b3);
        }
    }

    // epilogue: add bias, store (guard last n-tile)
    const int nb = n0 + tx * 8;
    const bool full = (n0 + 128 <= N_OUT);
    float fb[8];
    if (full) {
        *(float4*)(fb)     = *(const float4*)(fc_b + nb);
        *(float4*)(fb + 4) = *(const float4*)(fc_b + nb + 4);
    } else {
#pragma unroll
        for (int j = 0; j < 8; ++j) fb[j] = (nb + j < N_OUT) ? fc_b[nb + j] : 0.f;
    }

#pragma unroll
    for (int mi = 0; mi < 8; ++mi) {
        int m = m0 + ty * 8 + mi;
        float r[8];
#pragma unroll
        for (int p = 0; p < 4; ++p) {
            float2 v = *(float2*)&acc[mi][p];
            r[2 * p]     = v.x + fb[2 * p];
            r[2 * p + 1] = v.y + fb[2 * p + 1];
        }
        float* op = out + (size_t)m * N_OUT + nb;
        if (full) {
#pragma unroll
            for (int p = 0; p < 4; ++p) {
                float2 v2 = make_float2(r[2 * p], r[2 * p + 1]);
                *(float2*)(op + 2 * p) = v2;   // 8B aligned (nb even)
            }
        } else {
#pragma unroll
            for (int j = 0; j < 8; ++j)
                if (nb + j < N_OUT) op[j] = r[j];
        }
    }
}

// ---------------------------------------------------------------------------
extern "C" void kernel_launch(void* const* d_in, const int* in_sizes, int n_in,
                              void* d_out, int out_size) {
    const float* x          = (const float*)d_in[0];
    const float* conv_w     = (const float*)d_in[1];
    const float* bn_gamma   = (const float*)d_in[2];
    const float* bn_beta    = (const float*)d_in[3];
    const float* bn_mean    = (const float*)d_in[4];
    const float* bn_var     = (const float*)d_in[5];
    const float* in_proj_w  = (const float*)d_in[6];
    const float* in_proj_b  = (const float*)d_in[7];
    const float* out_proj_w = (const float*)d_in[8];
    const float* out_proj_b = (const float*)d_in[9];
    const float* fc_w       = (const float*)d_in[10];
    const float* fc_b       = (const float*)d_in[11];
    float* out = (float*)d_out;

    const int smem_bytes = K_DIM * 128 * 2 * (int)sizeof(float);  // 184320
    cudaFuncSetAttribute(fc_kernel, cudaFuncAttributeMaxDynamicSharedMemorySize,
                         smem_bytes);

    transpose_fcw_kernel<<<(K_DIM * NPAD + 255) / 256, 256>>>(fc_w);
    head_kernel<<<B_BATCH, 96>>>(x, conv_w, bn_gamma, bn_beta, bn_mean, bn_var,
                                 in_proj_w, in_proj_b, out_proj_w, out_proj_b);
    fc_kernel<<<dim3((N_OUT + 127) / 128, B_BATCH / 128), 256, smem_bytes>>>(
        fc_b, out);
}

// round 3
// speedup vs baseline: 1.2442x; 1.2442x over previous
#include <cuda_runtime.h>
#include <cuda_bf16.h>
#include <cstdint>

// Problem constants
#define C_IN    256
#define S_SEQ   90
#define K_DIM   180
#define B_BATCH 4096
#define N_OUT   2086
#define MT      (B_BATCH / 128)        // 32 m-tiles
#define NT      ((N_OUT + 127) / 128)  // 17 n-tiles
#define PITCH   200                    // row pitch in bf16 elems (400B -> conflict-free ldmatrix)
#define TILE_E  (128 * PITCH)          // elems per tile image

// Tile images: [row][k] bf16, pitch 200. k in [180,192) must stay ZERO (zero-init,
// never written) because the GEMM consumes k in [0,192).
__device__ __align__(16) __nv_bfloat16 g_Ahi[MT * TILE_E];
__device__ __align__(16) __nv_bfloat16 g_Alo[MT * TILE_E];
__device__ __align__(16) __nv_bfloat16 g_Bhi[NT * TILE_E];
__device__ __align__(16) __nv_bfloat16 g_Blo[NT * TILE_E];

__device__ __forceinline__ void store_split(__nv_bfloat16* hi_arr,
                                            __nv_bfloat16* lo_arr,
                                            size_t idx, float v) {
    __nv_bfloat16 hi = __float2bfloat16(v);
    hi_arr[idx] = hi;
    lo_arr[idx] = __float2bfloat16(v - __bfloat162float(hi));
}

// ---------------------------------------------------------------------------
// Kernel: fc_w [2086,180] -> bf16 hi/lo tile images
// ---------------------------------------------------------------------------
__global__ void prep_b_kernel(const float* __restrict__ fc_w) {
    int i = blockIdx.x * 256 + threadIdx.x;
    if (i >= N_OUT * K_DIM) return;
    int n = i / K_DIM;
    int k = i - n * K_DIM;
    size_t idx = (size_t)(n >> 7) * TILE_E + (n & 127) * PITCH + k;
    store_split(g_Bhi, g_Blo, idx, fc_w[i]);
}

// ---------------------------------------------------------------------------
// Kernel: conv1x1 + BN + attention(head_dim=1) + out_proj -> bf16 hi/lo A tiles
// ---------------------------------------------------------------------------
__global__ __launch_bounds__(96) void head_kernel(
    const float* __restrict__ x,
    const float* __restrict__ conv_w,
    const float* __restrict__ bn_gamma, const float* __restrict__ bn_beta,
    const float* __restrict__ bn_mean,  const float* __restrict__ bn_var,
    const float* __restrict__ in_proj_w, const float* __restrict__ in_proj_b,
    const float* __restrict__ out_proj_w, const float* __restrict__ out_proj_b)
{
    __shared__ float sw0[C_IN], sw1[C_IN];
    __shared__ float sk0[S_SEQ], sk1[S_SEQ], sv0[S_SEQ], sv1[S_SEQ];
    __shared__ float sred[4];

    const int b = blockIdx.x;
    const int t = threadIdx.x;

    for (int i = t; i < C_IN; i += 96) {
        sw0[i] = conv_w[i];
        sw1[i] = conv_w[C_IN + i];
    }
    __syncthreads();

    float q0 = 0.f, q1 = 0.f;
    if (t < S_SEQ) {
        const float* xb = x + (size_t)b * (C_IN * S_SEQ) + t;
        float a0 = 0.f, a1 = 0.f;
#pragma unroll 16
        for (int c = 0; c < C_IN; ++c) {
            float xv = __ldg(xb + c * S_SEQ);
            a0 = fmaf(sw0[c], xv, a0);
            a1 = fmaf(sw1[c], xv, a1);
        }
        float s0 = bn_gamma[0] * rsqrtf(bn_var[0] + 1e-5f);
        float s1 = bn_gamma[1] * rsqrtf(bn_var[1] + 1e-5f);
        float y0 = fmaf(a0, s0, bn_beta[0] - bn_mean[0] * s0);
        float y1 = fmaf(a1, s1, bn_beta[1] - bn_mean[1] * s1);
        q0     = fmaf(y0, in_proj_w[0],  fmaf(y1, in_proj_w[1],  in_proj_b[0]));
        q1     = fmaf(y0, in_proj_w[2],  fmaf(y1, in_proj_w[3],  in_proj_b[1]));
        sk0[t] = fmaf(y0, in_proj_w[4],  fmaf(y1, in_proj_w[5],  in_proj_b[2]));
        sk1[t] = fmaf(y0, in_proj_w[6],  fmaf(y1, in_proj_w[7],  in_proj_b[3]));
        sv0[t] = fmaf(y0, in_proj_w[8],  fmaf(y1, in_proj_w[9],  in_proj_b[4]));
        sv1[t] = fmaf(y0, in_proj_w[10], fmaf(y1, in_proj_w[11], in_proj_b[5]));
    }
    __syncthreads();

    if (t < 64) {
        int h = t >> 5, lane = t & 31;
        const float* kk = h ? sk1 : sk0;
        float mx = -3.4e38f, mn = 3.4e38f;
        for (int j = lane; j < S_SEQ; j += 32) {
            float kv = kk[j];
            mx = fmaxf(mx, kv);
            mn = fminf(mn, kv);
        }
        for (int o = 16; o > 0; o >>= 1) {
            mx = fmaxf(mx, __shfl_xor_sync(0xffffffffu, mx, o));
            mn = fminf(mn, __shfl_xor_sync(0xffffffffu, mn, o));
        }
        if (lane == 0) { sred[h * 2] = mx; sred[h * 2 + 1] = mn; }
    }
    __syncthreads();

    if (t < S_SEQ) {
        float m0 = fmaxf(q0 * sred[0], q0 * sred[1]);
        float m1 = fmaxf(q1 * sred[2], q1 * sred[3]);
        float d0 = 0.f, n0 = 0.f, d1 = 0.f, n1 = 0.f;
#pragma unroll 5
        for (int j = 0; j < S_SEQ; ++j) {
            float e0 = __expf(fmaf(q0, sk0[j], -m0));
            float e1 = __expf(fmaf(q1, sk1[j], -m1));
            d0 += e0; n0 = fmaf(e0, sv0[j], n0);
            d1 += e1; n1 = fmaf(e1, sv1[j], n1);
        }
        float o0 = n0 / d0, o1 = n1 / d1;
        float f0 = fmaf(o0, out_proj_w[0], fmaf(o1, out_proj_w[1], out_proj_b[0]));
        float f1 = fmaf(o0, out_proj_w[2], fmaf(o1, out_proj_w[3], out_proj_b[1]));
        size_t base = (size_t)(b >> 7) * TILE_E + (size_t)(b & 127) * PITCH;
        store_split(g_Ahi, g_Alo, base + t,         f0);  // k = s
        store_split(g_Ahi, g_Alo, base + S_SEQ + t, f1);  // k = 90 + s
    }
}

// ---------------------------------------------------------------------------
// FC GEMM: mma.sync m16n8k16 bf16, hi/lo split (3 terms), fp32 accum.
// Grid (NT, MT), 256 threads (8 warps), CTA tile 128x128, warp tile 64x32.
// ---------------------------------------------------------------------------
#define OFF_AHI 0
#define OFF_ALO 51200
#define OFF_BHI 102400
#define OFF_BLO 153600
#define SMEM_TOTAL 204800

__device__ __forceinline__ uint32_t smem_u32(const void* p) {
    uint32_t a;
    asm("{ .reg .u64 t; cvta.to.shared.u64 t, %1; cvt.u32.u64 %0, t; }"
        : "=r"(a) : "l"(p));
    return a;
}

#define LDSM4(r, addr)                                                         \
    asm volatile("ldmatrix.sync.aligned.m8n8.x4.shared.b16 {%0,%1,%2,%3}, [%4];" \
                 : "=r"((r)[0]), "=r"((r)[1]), "=r"((r)[2]), "=r"((r)[3])      \
                 : "r"(addr))

#define MMA16816(c, a, b0v, b1v)                                               \
    asm volatile(                                                              \
        "mma.sync.aligned.m16n8k16.row.col.f32.bf16.bf16.f32 "                 \
        "{%0,%1,%2,%3}, {%4,%5,%6,%7}, {%8,%9}, {%0,%1,%2,%3};"                \
        : "+f"((c)[0]), "+f"((c)[1]), "+f"((c)[2]), "+f"((c)[3])               \
        : "r"((a)[0]), "r"((a)[1]), "r"((a)[2]), "r"((a)[3]),                  \
          "r"(b0v), "r"(b1v))

__global__ __launch_bounds__(256, 1) void fc_mma_kernel(
    const float* __restrict__ fc_b, float* __restrict__ out)
{
    extern __shared__ char sm[];
    const uint32_t sb = smem_u32(sm);
    const int tid = threadIdx.x;
    const int wid = tid >> 5;
    const int l   = tid & 31;
    const int nt = blockIdx.x, mt = blockIdx.y;
    const int n0 = nt * 128, m0 = mt * 128;

    // Stage all four tile images (contiguous float4, fully coalesced)
    {
        const float4* gAh = (const float4*)(g_Ahi + (size_t)mt * TILE_E);
        const float4* gAl = (const float4*)(g_Alo + (size_t)mt * TILE_E);
        const float4* gBh = (const float4*)(g_Bhi + (size_t)nt * TILE_E);
        const float4* gBl = (const float4*)(g_Blo + (size_t)nt * TILE_E);
        float4* dAh = (float4*)(sm + OFF_AHI);
        float4* dAl = (float4*)(sm + OFF_ALO);
        float4* dBh = (float4*)(sm + OFF_BHI);
        float4* dBl = (float4*)(sm + OFF_BLO);
        for (int i = tid; i < 3200; i += 256) {
            dAh[i] = gAh[i];
            dAl[i] = gAl[i];
            dBh[i] = gBh[i];
            dBl[i] = gBl[i];
        }
    }
    __syncthreads();

    const int wm = wid & 1;        // 2 m-blocks of 64
    const int wn = wid >> 1;       // 4 n-blocks of 32

    // Per-lane ldmatrix base offsets (bytes). Pitch = 400B.
    // A x4: lanes 0-15 rows (l&15) at k0; lanes 16-31 same rows at k0+8.
    const uint32_t aoff = (uint32_t)((wm * 64 + (l & 15)) * 400 + ((l >> 4) & 1) * 16);
    // B x4: lanes 0-7 n-rows 0-7 @k0; 8-15 @k0+8; 16-23 rows 8-15 @k0; 24-31 @k0+8.
    const uint32_t boff = (uint32_t)((wn * 32 + (l & 7) + ((l >> 4) & 1) * 8) * 400
                                     + ((l >> 3) & 1) * 16);

    const uint32_t aAh = sb + OFF_AHI + aoff;
    const uint32_t aAl = sb + OFF_ALO + aoff;
    const uint32_t bBh = sb + OFF_BHI + boff;
    const uint32_t bBl = sb + OFF_BLO + boff;

    float acc[4][4][4];
#pragma unroll
    for (int i = 0; i < 4; ++i)
#pragma unroll
        for (int j = 0; j < 4; ++j)
#pragma unroll
            for (int r = 0; r < 4; ++r) acc[i][j][r] = 0.f;

    const uint32_t Abases[3] = {aAh, aAh, aAl};
    const uint32_t Bbases[3] = {bBh, bBl, bBh};

#pragma unroll
    for (int t3 = 0; t3 < 3; ++t3) {
        const uint32_t Ab = Abases[t3];
        const uint32_t Bb = Bbases[t3];
#pragma unroll 4
        for (int ks = 0; ks < 12; ++ks) {
            const uint32_t ko = ks * 32;   // 16 bf16 = 32 bytes
            uint32_t a[4][4];
#pragma unroll
            for (int mi = 0; mi < 4; ++mi) LDSM4(a[mi], Ab + mi * 6400 + ko);
            uint32_t bq0[4], bq1[4];
            LDSM4(bq0, Bb + ko);          // n-tiles 0,1
            LDSM4(bq1, Bb + 6400 + ko);   // n-tiles 2,3
#pragma unroll
            for (int mi = 0; mi < 4; ++mi) {
                MMA16816(acc[mi][0], a[mi], bq0[0], bq0[1]);
                MMA16816(acc[mi][1], a[mi], bq0[2], bq0[3]);
                MMA16816(acc[mi][2], a[mi], bq1[0], bq1[1]);
                MMA16816(acc[mi][3], a[mi], bq1[2], bq1[3]);
            }
        }
    }

    // Epilogue: direct stores + bias. C frag: c0,c1 -> row l/4, cols (l&3)*2,+1;
    // c2,c3 -> row l/4+8.
    const int nvalid = N_OUT - n0;           // 128 except last tile (38)
#pragma unroll
    for (int ni = 0; ni < 4; ++ni) {
        const int n = wn * 32 + ni * 8 + (l & 3) * 2;
        if (n < nvalid) {
            const float b0 = __ldg(fc_b + n0 + n);
            const float b1 = __ldg(fc_b + n0 + n + 1);
#pragma unroll
            for (int mi = 0; mi < 4; ++mi) {
                const int m = m0 + wm * 64 + mi * 16 + (l >> 2);
                float* p0 = out + (size_t)m * N_OUT + n0 + n;
                float* p1 = out + (size_t)(m + 8) * N_OUT + n0 + n;
                *(float2*)p0 = make_float2(acc[mi][ni][0] + b0, acc[mi][ni][1] + b1);
                *(float2*)p1 = make_float2(acc[mi][ni][2] + b0, acc[mi][ni][3] + b1);
            }
        }
    }
}

// ---------------------------------------------------------------------------
extern "C" void kernel_launch(void* const* d_in, const int* in_sizes, int n_in,
                              void* d_out, int out_size) {
    const float* x          = (const float*)d_in[0];
    const float* conv_w     = (const float*)d_in[1];
    const float* bn_gamma   = (const float*)d_in[2];
    const float* bn_beta    = (const float*)d_in[3];
    const float* bn_mean    = (const float*)d_in[4];
    const float* bn_var     = (const float*)d_in[5];
    const float* in_proj_w  = (const float*)d_in[6];
    const float* in_proj_b  = (const float*)d_in[7];
    const float* out_proj_w = (const float*)d_in[8];
    const float* out_proj_b = (const float*)d_in[9];
    const float* fc_w       = (const float*)d_in[10];
    const float* fc_b       = (const float*)d_in[11];
    float* out = (float*)d_out;

    cudaFuncSetAttribute(fc_mma_kernel,
                         cudaFuncAttributeMaxDynamicSharedMemorySize, SMEM_TOTAL);

    head_kernel<<<B_BATCH, 96>>>(x, conv_w, bn_gamma, bn_beta, bn_mean, bn_var,
                                 in_proj_w, in_proj_b, out_proj_w, out_proj_b);
    prep_b_kernel<<<(N_OUT * K_DIM + 255) / 256, 256>>>(fc_w);
    fc_mma_kernel<<<dim3(NT, MT), 256, SMEM_TOTAL>>>(fc_b, out);
}

// round 4
// speedup vs baseline: 1.4772x; 1.1872x over previous
#include <cuda_runtime.h>
#include <cuda_bf16.h>
#include <cstdint>

// Problem constants
#define C_IN    256
#define S_SEQ   90
#define K_DIM   180
#define B_BATCH 4096
#define N_OUT   2086
#define MT      (B_BATCH / 128)        // 32 m-tiles
#define NT      ((N_OUT + 127) / 128)  // 17 n-tiles
#define PITCH   200                    // row pitch in bf16 elems (400B -> conflict-free ldmatrix)
#define TILE_E  (128 * PITCH)          // elems per tile image

// Tile images: [row][k] bf16, pitch 200. k in [180,192) must stay ZERO (zero-init,
// never written) because the GEMM consumes k in [0,192).
__device__ __align__(16) __nv_bfloat16 g_Ahi[MT * TILE_E];
__device__ __align__(16) __nv_bfloat16 g_Alo[MT * TILE_E];
__device__ __align__(16) __nv_bfloat16 g_Bhi[NT * TILE_E];
__device__ __align__(16) __nv_bfloat16 g_Blo[NT * TILE_E];

__device__ __forceinline__ void store_split(__nv_bfloat16* hi_arr,
                                            __nv_bfloat16* lo_arr,
                                            size_t idx, float v) {
    __nv_bfloat16 hi = __float2bfloat16(v);
    hi_arr[idx] = hi;
    lo_arr[idx] = __float2bfloat16(v - __bfloat162float(hi));
}

// ---------------------------------------------------------------------------
// Kernel: fc_w [2086,180] -> bf16 hi/lo tile images
// ---------------------------------------------------------------------------
__global__ void prep_b_kernel(const float* __restrict__ fc_w) {
    int i = blockIdx.x * 256 + threadIdx.x;
    if (i >= N_OUT * K_DIM) return;
    int n = i / K_DIM;
    int k = i - n * K_DIM;
    size_t idx = (size_t)(n >> 7) * TILE_E + (n & 127) * PITCH + k;
    store_split(g_Bhi, g_Blo, idx, fc_w[i]);
}

// ---------------------------------------------------------------------------
// Kernel: conv1x1 + BN + attention(head_dim=1) + out_proj -> bf16 hi/lo A tiles
// 384 threads: thread (cc, s) accumulates 64 channels of the 1x1 conv; 4-way
// smem reduction; attention done by threads 0..89.
// ---------------------------------------------------------------------------
__global__ __launch_bounds__(384) void head_kernel(
    const float* __restrict__ x,
    const float* __restrict__ conv_w,
    const float* __restrict__ bn_gamma, const float* __restrict__ bn_beta,
    const float* __restrict__ bn_mean,  const float* __restrict__ bn_var,
    const float* __restrict__ in_proj_w, const float* __restrict__ in_proj_b,
    const float* __restrict__ out_proj_w, const float* __restrict__ out_proj_b)
{
    __shared__ float sw0[C_IN], sw1[C_IN];
    __shared__ float part0[4][96], part1[4][96];
    __shared__ float sk0[S_SEQ], sk1[S_SEQ], sv0[S_SEQ], sv1[S_SEQ];
    __shared__ float sred[4];

    const int b   = blockIdx.x;
    const int tid = threadIdx.x;
    const int cc  = tid / 96;       // channel chunk 0..3
    const int s   = tid - cc * 96;  // 0..95 (s<90 active)

    for (int i = tid; i < C_IN; i += 384) {
        sw0[i] = conv_w[i];
        sw1[i] = conv_w[C_IN + i];
    }
    __syncthreads();

    {
        float a0 = 0.f, a1 = 0.f;
        if (s < S_SEQ) {
            const float* xb = x + (size_t)b * (C_IN * S_SEQ) + cc * (64 * S_SEQ) + s;
            const float* w0 = sw0 + cc * 64;
            const float* w1 = sw1 + cc * 64;
#pragma unroll 16
            for (int c = 0; c < 64; ++c) {
                float xv = __ldg(xb + c * S_SEQ);
                a0 = fmaf(w0[c], xv, a0);
                a1 = fmaf(w1[c], xv, a1);
            }
        }
        part0[cc][s] = a0;
        part1[cc][s] = a1;
    }
    __syncthreads();

    float q0 = 0.f, q1 = 0.f;
    if (tid < S_SEQ) {
        float a0 = part0[0][tid] + part0[1][tid] + part0[2][tid] + part0[3][tid];
        float a1 = part1[0][tid] + part1[1][tid] + part1[2][tid] + part1[3][tid];
        float s0 = bn_gamma[0] * rsqrtf(bn_var[0] + 1e-5f);
        float s1 = bn_gamma[1] * rsqrtf(bn_var[1] + 1e-5f);
        float y0 = fmaf(a0, s0, bn_beta[0] - bn_mean[0] * s0);
        float y1 = fmaf(a1, s1, bn_beta[1] - bn_mean[1] * s1);
        q0       = fmaf(y0, in_proj_w[0],  fmaf(y1, in_proj_w[1],  in_proj_b[0]));
        q1       = fmaf(y0, in_proj_w[2],  fmaf(y1, in_proj_w[3],  in_proj_b[1]));
        sk0[tid] = fmaf(y0, in_proj_w[4],  fmaf(y1, in_proj_w[5],  in_proj_b[2]));
        sk1[tid] = fmaf(y0, in_proj_w[6],  fmaf(y1, in_proj_w[7],  in_proj_b[3]));
        sv0[tid] = fmaf(y0, in_proj_w[8],  fmaf(y1, in_proj_w[9],  in_proj_b[4]));
        sv1[tid] = fmaf(y0, in_proj_w[10], fmaf(y1, in_proj_w[11], in_proj_b[5]));
    }
    __syncthreads();

    // per-head k max/min for exact stable softmax
    if (tid < 64) {
        int h = tid >> 5, lane = tid & 31;
        const float* kk = h ? sk1 : sk0;
        float mx = -3.4e38f, mn = 3.4e38f;
        for (int j = lane; j < S_SEQ; j += 32) {
            float kv = kk[j];
            mx = fmaxf(mx, kv);
            mn = fminf(mn, kv);
        }
        for (int o = 16; o > 0; o >>= 1) {
            mx = fmaxf(mx, __shfl_xor_sync(0xffffffffu, mx, o));
            mn = fminf(mn, __shfl_xor_sync(0xffffffffu, mn, o));
        }
        if (lane == 0) { sred[h * 2] = mx; sred[h * 2 + 1] = mn; }
    }
    __syncthreads();

    if (tid < S_SEQ) {
        float m0 = fmaxf(q0 * sred[0], q0 * sred[1]);
        float m1 = fmaxf(q1 * sred[2], q1 * sred[3]);
        float d0 = 0.f, n0 = 0.f, d1 = 0.f, n1 = 0.f;
#pragma unroll 5
        for (int j = 0; j < S_SEQ; ++j) {
            float e0 = __expf(fmaf(q0, sk0[j], -m0));
            float e1 = __expf(fmaf(q1, sk1[j], -m1));
            d0 += e0; n0 = fmaf(e0, sv0[j], n0);
            d1 += e1; n1 = fmaf(e1, sv1[j], n1);
        }
        float o0 = n0 / d0, o1 = n1 / d1;
        float f0 = fmaf(o0, out_proj_w[0], fmaf(o1, out_proj_w[1], out_proj_b[0]));
        float f1 = fmaf(o0, out_proj_w[2], fmaf(o1, out_proj_w[3], out_proj_b[1]));
        size_t base = (size_t)(b >> 7) * TILE_E + (size_t)(b & 127) * PITCH;
        store_split(g_Ahi, g_Alo, base + tid,         f0);  // k = s
        store_split(g_Ahi, g_Alo, base + S_SEQ + tid, f1);  // k = 90 + s
    }
}

// ---------------------------------------------------------------------------
// FC GEMM: mma.sync m16n8k16 bf16, hi/lo split (3 terms), fp32 accum.
// cp.async two-stage pipeline: (Ahi,Bhi) then (Alo,Blo); hi*hi overlaps lo load.
// Grid (NT, MT), 256 threads (8 warps), CTA tile 128x128, warp tile 64x32.
// ---------------------------------------------------------------------------
#define OFF_AHI 0
#define OFF_ALO 51200
#define OFF_BHI 102400
#define OFF_BLO 153600
#define SMEM_TOTAL 204800

__device__ __forceinline__ uint32_t smem_u32(const void* p) {
    uint32_t a;
    asm("{ .reg .u64 t; cvta.to.shared.u64 t, %1; cvt.u32.u64 %0, t; }"
        : "=r"(a) : "l"(p));
    return a;
}

#define CP16(dst, src)                                                         \
    asm volatile("cp.async.cg.shared.global [%0], [%1], 16;"                   \
                 :: "r"(dst), "l"(src))

#define LDSM4(r, addr)                                                         \
    asm volatile("ldmatrix.sync.aligned.m8n8.x4.shared.b16 {%0,%1,%2,%3}, [%4];" \
                 : "=r"((r)[0]), "=r"((r)[1]), "=r"((r)[2]), "=r"((r)[3])      \
                 : "r"(addr))

#define MMA16816(c, a, b0v, b1v)                                               \
    asm volatile(                                                              \
        "mma.sync.aligned.m16n8k16.row.col.f32.bf16.bf16.f32 "                 \
        "{%0,%1,%2,%3}, {%4,%5,%6,%7}, {%8,%9}, {%0,%1,%2,%3};"                \
        : "+f"((c)[0]), "+f"((c)[1]), "+f"((c)[2]), "+f"((c)[3])               \
        : "r"((a)[0]), "r"((a)[1]), "r"((a)[2]), "r"((a)[3]),                  \
          "r"(b0v), "r"(b1v))

__global__ __launch_bounds__(256, 1) void fc_mma_kernel(
    const float* __restrict__ fc_b, float* __restrict__ out)
{
    extern __shared__ char sm[];
    const uint32_t sb = smem_u32(sm);
    const int tid = threadIdx.x;
    const int wid = tid >> 5;
    const int l   = tid & 31;
    const int nt = blockIdx.x, mt = blockIdx.y;
    const int n0 = nt * 128, m0 = mt * 128;

    // Pipelined staging: hi images (group 0), lo images (group 1)
    {
        const float4* gAh = (const float4*)(g_Ahi + (size_t)mt * TILE_E);
        const float4* gBh = (const float4*)(g_Bhi + (size_t)nt * TILE_E);
        for (int i = tid; i < 3200; i += 256) {
            CP16(sb + OFF_AHI + i * 16, gAh + i);
            CP16(sb + OFF_BHI + i * 16, gBh + i);
        }
        asm volatile("cp.async.commit_group;" ::: "memory");
        const float4* gAl = (const float4*)(g_Alo + (size_t)mt * TILE_E);
        const float4* gBl = (const float4*)(g_Blo + (size_t)nt * TILE_E);
        for (int i = tid; i < 3200; i += 256) {
            CP16(sb + OFF_ALO + i * 16, gAl + i);
            CP16(sb + OFF_BLO + i * 16, gBl + i);
        }
        asm volatile("cp.async.commit_group;" ::: "memory");
    }

    const int wm = wid & 1;        // 2 m-blocks of 64
    const int wn = wid >> 1;       // 4 n-blocks of 32

    const uint32_t aoff = (uint32_t)((wm * 64 + (l & 15)) * 400 + ((l >> 4) & 1) * 16);
    const uint32_t boff = (uint32_t)((wn * 32 + (l & 7) + ((l >> 4) & 1) * 8) * 400
                                     + ((l >> 3) & 1) * 16);

    const uint32_t aAh = sb + OFF_AHI + aoff;
    const uint32_t aAl = sb + OFF_ALO + aoff;
    const uint32_t bBh = sb + OFF_BHI + boff;
    const uint32_t bBl = sb + OFF_BLO + boff;

    float acc[4][4][4];
#pragma unroll
    for (int i = 0; i < 4; ++i)
#pragma unroll
        for (int j = 0; j < 4; ++j)
#pragma unroll
            for (int r = 0; r < 4; ++r) acc[i][j][r] = 0.f;

    // ---- term 0: hi*hi (lo images still in flight) ----
    asm volatile("cp.async.wait_group 1;" ::: "memory");
    __syncthreads();
#pragma unroll 4
    for (int ks = 0; ks < 12; ++ks) {
        const uint32_t ko = ks * 32;
        uint32_t a[4][4];
#pragma unroll
        for (int mi = 0; mi < 4; ++mi) LDSM4(a[mi], aAh + mi * 6400 + ko);
        uint32_t bq0[4], bq1[4];
        LDSM4(bq0, bBh + ko);
        LDSM4(bq1, bBh + 6400 + ko);
#pragma unroll
        for (int mi = 0; mi < 4; ++mi) {
            MMA16816(acc[mi][0], a[mi], bq0[0], bq0[1]);
            MMA16816(acc[mi][1], a[mi], bq0[2], bq0[3]);
            MMA16816(acc[mi][2], a[mi], bq1[0], bq1[1]);
            MMA16816(acc[mi][3], a[mi], bq1[2], bq1[3]);
        }
    }

    // ---- terms 1,2: hi*lo + lo*hi ----
    asm volatile("cp.async.wait_group 0;" ::: "memory");
    __syncthreads();
#pragma unroll
    for (int t3 = 0; t3 < 2; ++t3) {
        const uint32_t Ab = t3 ? aAl : aAh;
        const uint32_t Bb = t3 ? bBh : bBl;
#pragma unroll 4
        for (int ks = 0; ks < 12; ++ks) {
            const uint32_t ko = ks * 32;
            uint32_t a[4][4];
#pragma unroll
            for (int mi = 0; mi < 4; ++mi) LDSM4(a[mi], Ab + mi * 6400 + ko);
            uint32_t bq0[4], bq1[4];
            LDSM4(bq0, Bb + ko);
            LDSM4(bq1, Bb + 6400 + ko);
#pragma unroll
            for (int mi = 0; mi < 4; ++mi) {
                MMA16816(acc[mi][0], a[mi], bq0[0], bq0[1]);
                MMA16816(acc[mi][1], a[mi], bq0[2], bq0[3]);
                MMA16816(acc[mi][2], a[mi], bq1[0], bq1[1]);
                MMA16816(acc[mi][3], a[mi], bq1[2], bq1[3]);
            }
        }
    }

    // Epilogue: direct stores + bias.
    const int nvalid = N_OUT - n0;
#pragma unroll
    for (int ni = 0; ni < 4; ++ni) {
        const int n = wn * 32 + ni * 8 + (l & 3) * 2;
        if (n < nvalid) {
            const float b0 = __ldg(fc_b + n0 + n);
            const float b1 = __ldg(fc_b + n0 + n + 1);
#pragma unroll
            for (int mi = 0; mi < 4; ++mi) {
                const int m = m0 + wm * 64 + mi * 16 + (l >> 2);
                float* p0 = out + (size_t)m * N_OUT + n0 + n;
                float* p1 = out + (size_t)(m + 8) * N_OUT + n0 + n;
                *(float2*)p0 = make_float2(acc[mi][ni][0] + b0, acc[mi][ni][1] + b1);
                *(float2*)p1 = make_float2(acc[mi][ni][2] + b0, acc[mi][ni][3] + b1);
            }
        }
    }
}

// ---------------------------------------------------------------------------
extern "C" void kernel_launch(void* const* d_in, const int* in_sizes, int n_in,
                              void* d_out, int out_size) {
    const float* x          = (const float*)d_in[0];
    const float* conv_w     = (const float*)d_in[1];
    const float* bn_gamma   = (const float*)d_in[2];
    const float* bn_beta    = (const float*)d_in[3];
    const float* bn_mean    = (const float*)d_in[4];
    const float* bn_var     = (const float*)d_in[5];
    const float* in_proj_w  = (const float*)d_in[6];
    const float* in_proj_b  = (const float*)d_in[7];
    const float* out_proj_w = (const float*)d_in[8];
    const float* out_proj_b = (const float*)d_in[9];
    const float* fc_w       = (const float*)d_in[10];
    const float* fc_b       = (const float*)d_in[11];
    float* out = (float*)d_out;

    cudaFuncSetAttribute(fc_mma_kernel,
                         cudaFuncAttributeMaxDynamicSharedMemorySize, SMEM_TOTAL);

    prep_b_kernel<<<(N_OUT * K_DIM + 255) / 256, 256>>>(fc_w);
    head_kernel<<<B_BATCH, 384>>>(x, conv_w, bn_gamma, bn_beta, bn_mean, bn_var,
                                  in_proj_w, in_proj_b, out_proj_w, out_proj_b);
    fc_mma_kernel<<<dim3(NT, MT), 256, SMEM_TOTAL>>>(fc_b, out);
}